// round 1
// baseline (speedup 1.0000x reference)
#include <cuda_runtime.h>
#include <cstddef>

#define N_NODES   100000
#define N_EDGES   50000
#define N_INC     3200000
#define D_IN      128
#define D_HID     32
#define N_CLASSES 40

// ---------------------------------------------------------------------------
// Scratch (static device globals — no allocation allowed)
// ---------------------------------------------------------------------------
__device__ float g_xw[N_NODES * 40];     // XW for each layer (max F = 40) : 16 MB
__device__ float g_ef[N_EDGES * 40];     // hyperedge features              :  8 MB
__device__ float g_h1[N_NODES * D_HID];  // hidden layer                    : 12.8 MB
__device__ float g_dinv[N_NODES];        // 1/deg(node)
__device__ float g_binv[N_EDGES];        // 1/size(edge)

// ---------------------------------------------------------------------------
// 128-bit global reduction (no return): red.global.add.v4.f32
// ---------------------------------------------------------------------------
__device__ __forceinline__ void red_add_v4(float* addr, float4 v) {
    asm volatile("red.global.add.v4.f32 [%0], {%1, %2, %3, %4};"
                 :: "l"(addr), "f"(v.x), "f"(v.y), "f"(v.z), "f"(v.w)
                 : "memory");
}

// ---------------------------------------------------------------------------
// Small dense GEMM: Y[N,F] = X[N,K] @ W[K,F]   (W row-major [K,F])
// Block: F x RPB threads; W + an RPB-row X tile staged in smem.
// ---------------------------------------------------------------------------
template <int K, int F, int RPB>
__global__ void gemm_kernel(const float* __restrict__ X,
                            const float* __restrict__ W,
                            float* __restrict__ Y, int N) {
    __shared__ float ws[K * F];
    __shared__ float xs[RPB * K];
    const int tx  = threadIdx.x;            // 0..F-1  (output column)
    const int ty  = threadIdx.y;            // 0..RPB-1 (row within tile)
    const int tid = ty * F + tx;
    const int nth = F * RPB;

    for (int i = tid; i < K * F; i += nth) ws[i] = W[i];

    const int row0 = blockIdx.x * RPB;
    for (int i = tid; i < RPB * K; i += nth) {
        int r = row0 + i / K;
        xs[i] = (r < N) ? X[(size_t)r * K + (i % K)] : 0.0f;
    }
    __syncthreads();

    float acc = 0.0f;
#pragma unroll
    for (int k = 0; k < K; k++)
        acc += xs[ty * K + k] * ws[k * F + tx];

    const int row = row0 + ty;
    if (row < N) Y[(size_t)row * F + tx] = acc;
}

// ---------------------------------------------------------------------------
// Degree histograms (float, RED — result unused)
// ---------------------------------------------------------------------------
__global__ void degree_kernel(const int* __restrict__ nidx,
                              const int* __restrict__ eidx,
                              float* __restrict__ dn,
                              float* __restrict__ de, int n) {
    int i = blockIdx.x * blockDim.x + threadIdx.x;
    if (i < n) {
        atomicAdd(dn + nidx[i], 1.0f);
        atomicAdd(de + eidx[i], 1.0f);
    }
}

__global__ void invert_kernel(float* __restrict__ a, int n) {
    int i = blockIdx.x * blockDim.x + threadIdx.x;
    if (i < n) {
        float d = a[i];
        a[i] = (d > 0.0f) ? (1.0f / d) : 0.0f;
    }
}

// ---------------------------------------------------------------------------
// Scatter: for each incidence pair i: dst[dst_idx[i]] += src[src_idx[i]]
// Warp handles 32 consecutive pairs: coalesced index load, then each pair is
// serviced by Q = F/4 lanes (float4 gather + v4 RED). F=32 -> 4 pairs/step
// all 32 lanes active; F=40 -> 3 pairs/step, 30 lanes active.
// ---------------------------------------------------------------------------
template <int F>
__global__ void scatter_kernel(const int* __restrict__ src_idx,
                               const int* __restrict__ dst_idx,
                               const float* __restrict__ src,
                               float* __restrict__ dst, int n) {
    constexpr int Q   = F / 4;     // float4 quads per row
    constexpr int PPW = 32 / Q;    // pairs serviced per warp step
    const int lane = threadIdx.x & 31;
    const int warp = (blockIdx.x * blockDim.x + threadIdx.x) >> 5;
    const int base = warp * 32;
    if (base >= n) return;

    const int li = base + lane;
    int s = (li < n) ? src_idx[li] : -1;
    int d = (li < n) ? dst_idx[li] : -1;

    const int sub = lane / Q;      // which pair within this step
    const int q   = lane % Q;      // which quad of the feature row

#pragma unroll
    for (int k0 = 0; k0 < 32; k0 += PPW) {
        const int k  = k0 + sub;
        const int ss = __shfl_sync(0xffffffffu, s, k & 31);
        const int dd = __shfl_sync(0xffffffffu, d, k & 31);
        if (sub < PPW && k < 32 && ss >= 0) {
            float4 v = *reinterpret_cast<const float4*>(src + (size_t)ss * F + q * 4);
            red_add_v4(dst + (size_t)dd * F + q * 4, v);
        }
    }
}

// ---------------------------------------------------------------------------
// Row-broadcast scale: a[r][:] *= s[r]
// ---------------------------------------------------------------------------
template <int F>
__global__ void scale_rows(float* __restrict__ a, const float* __restrict__ s,
                           int rows) {
    int i = blockIdx.x * blockDim.x + threadIdx.x;
    if (i < rows * F) a[i] *= s[i / F];
}

// ---------------------------------------------------------------------------
// Layer-1 finalize: h = relu(h * Dinv[node] + b1)   (F = 32, in-place)
// ---------------------------------------------------------------------------
__global__ void finalize_relu(float* __restrict__ h,
                              const float* __restrict__ dinv,
                              const float* __restrict__ b, int n) {
    int i = blockIdx.x * blockDim.x + threadIdx.x;
    if (i < n) {
        float v = h[i] * dinv[i >> 5] + b[i & 31];
        h[i] = (v > 0.0f) ? v : 0.0f;
    }
}

// ---------------------------------------------------------------------------
// Layer-2 finalize: out = log_softmax(out * Dinv[node] + b2), one warp/node.
// Lane l holds class l; lanes 0..7 additionally hold class l+32.
// ---------------------------------------------------------------------------
__global__ void finalize_logsoftmax(float* __restrict__ out,
                                    const float* __restrict__ dinv,
                                    const float* __restrict__ b) {
    const int warp = (blockIdx.x * blockDim.x + threadIdx.x) >> 5;
    const int lane = threadIdx.x & 31;
    if (warp >= N_NODES) return;

    const float di = dinv[warp];
    float* row = out + (size_t)warp * N_CLASSES;

    float z0 = row[lane] * di + b[lane];
    float z1 = (lane < N_CLASSES - 32) ? (row[lane + 32] * di + b[lane + 32])
                                       : -1e30f;
    float m = fmaxf(z0, z1);
#pragma unroll
    for (int o = 16; o; o >>= 1) m = fmaxf(m, __shfl_xor_sync(0xffffffffu, m, o));

    float e = __expf(z0 - m) + ((lane < N_CLASSES - 32) ? __expf(z1 - m) : 0.0f);
#pragma unroll
    for (int o = 16; o; o >>= 1) e += __shfl_xor_sync(0xffffffffu, e, o);

    const float lse = __logf(e) + m;
    row[lane] = z0 - lse;
    if (lane < N_CLASSES - 32) row[lane + 32] = z1 - lse;
}

// ---------------------------------------------------------------------------
// Launch
// ---------------------------------------------------------------------------
extern "C" void kernel_launch(void* const* d_in, const int* in_sizes, int n_in,
                              void* d_out, int out_size) {
    const float* x    = (const float*)d_in[0];
    const int*   nidx = (const int*)d_in[1];
    const int*   eidx = (const int*)d_in[2];
    const float* W1   = (const float*)d_in[3];
    const float* b1   = (const float*)d_in[4];
    const float* W2   = (const float*)d_in[5];
    const float* b2   = (const float*)d_in[6];
    float* out = (float*)d_out;

    float *xw, *ef, *h1, *dinv, *binv;
    cudaGetSymbolAddress((void**)&xw,   g_xw);
    cudaGetSymbolAddress((void**)&ef,   g_ef);
    cudaGetSymbolAddress((void**)&h1,   g_h1);
    cudaGetSymbolAddress((void**)&dinv, g_dinv);
    cudaGetSymbolAddress((void**)&binv, g_binv);

    const int scatter_blocks = (N_INC / 32 + 7) / 8;   // 32 pairs/warp, 8 warps/block

    // ---- degrees ----
    cudaMemsetAsync(dinv, 0, N_NODES * sizeof(float));
    cudaMemsetAsync(binv, 0, N_EDGES * sizeof(float));
    degree_kernel<<<(N_INC + 255) / 256, 256>>>(nidx, eidx, dinv, binv, N_INC);
    invert_kernel<<<(N_NODES + 255) / 256, 256>>>(dinv, N_NODES);
    invert_kernel<<<(N_EDGES + 255) / 256, 256>>>(binv, N_EDGES);

    // ---- layer 1: h1 = relu(Dinv H Binv H^T (x W1) + b1) ----
    gemm_kernel<D_IN, D_HID, 8><<<(N_NODES + 7) / 8, dim3(D_HID, 8)>>>(x, W1, xw, N_NODES);

    cudaMemsetAsync(ef, 0, (size_t)N_EDGES * D_HID * sizeof(float));
    scatter_kernel<D_HID><<<scatter_blocks, 256>>>(nidx, eidx, xw, ef, N_INC);
    scale_rows<D_HID><<<(N_EDGES * D_HID + 255) / 256, 256>>>(ef, binv, N_EDGES);

    cudaMemsetAsync(h1, 0, (size_t)N_NODES * D_HID * sizeof(float));
    scatter_kernel<D_HID><<<scatter_blocks, 256>>>(eidx, nidx, ef, h1, N_INC);
    finalize_relu<<<(N_NODES * D_HID + 255) / 256, 256>>>(h1, dinv, b1, N_NODES * D_HID);

    // ---- layer 2: out = log_softmax(Dinv H Binv H^T (h1 W2) + b2) ----
    gemm_kernel<D_HID, N_CLASSES, 8><<<(N_NODES + 7) / 8, dim3(N_CLASSES, 8)>>>(h1, W2, xw, N_NODES);

    cudaMemsetAsync(ef, 0, (size_t)N_EDGES * N_CLASSES * sizeof(float));
    scatter_kernel<N_CLASSES><<<scatter_blocks, 256>>>(nidx, eidx, xw, ef, N_INC);
    scale_rows<N_CLASSES><<<(N_EDGES * N_CLASSES + 255) / 256, 256>>>(ef, binv, N_EDGES);

    cudaMemsetAsync(out, 0, (size_t)N_NODES * N_CLASSES * sizeof(float));
    scatter_kernel<N_CLASSES><<<scatter_blocks, 256>>>(eidx, nidx, ef, out, N_INC);
    finalize_logsoftmax<<<(N_NODES + 7) / 8, 256>>>(out, dinv, b2);
}

// round 2
// speedup vs baseline: 1.3053x; 1.3053x over previous
#include <cuda_runtime.h>
#include <cstddef>

#define N_NODES   100000
#define N_EDGES   50000
#define N_INC     3200000
#define D_IN      128
#define D_HID     32
#define N_CLASSES 40
#define S2        64          // padded row stride for layer-2 (40 -> 64 floats)

// ---------------------------------------------------------------------------
// Scratch (static device globals)
// ---------------------------------------------------------------------------
__device__ float g_xw[(size_t)N_NODES * S2];   // XW (layer1 stride 32, layer2 stride 64)
__device__ float g_ef[(size_t)N_EDGES * S2];   // hyperedge features
__device__ float g_h1[(size_t)N_NODES * D_HID];
__device__ float g_dinv[N_NODES];
__device__ float g_binv[N_EDGES];

__device__ int g_cnt_n[N_NODES];
__device__ int g_cnt_e[N_EDGES];
__device__ int g_off_n[N_NODES + 1];
__device__ int g_off_e[N_EDGES + 1];
__device__ int g_cur_n[N_NODES];
__device__ int g_cur_e[N_EDGES];
__device__ int g_adj_n[N_INC];   // edge ids grouped by node
__device__ int g_adj_e[N_INC];   // node ids grouped by edge
__device__ int g_aux_n[128];
__device__ int g_aux_e[128];

// ---------------------------------------------------------------------------
// Degree counting (int) + inverse-degree floats
// ---------------------------------------------------------------------------
__global__ void degree_kernel(const int* __restrict__ nidx,
                              const int* __restrict__ eidx,
                              int* __restrict__ cn, int* __restrict__ ce, int n) {
    int i = blockIdx.x * blockDim.x + threadIdx.x;
    if (i < n) {
        atomicAdd(cn + nidx[i], 1);
        atomicAdd(ce + eidx[i], 1);
    }
}

__global__ void invert_kernel(const int* __restrict__ cnt, float* __restrict__ inv, int n) {
    int i = blockIdx.x * blockDim.x + threadIdx.x;
    if (i < n) {
        int d = cnt[i];
        inv[i] = (d > 0) ? (1.0f / (float)d) : 0.0f;
    }
}

// ---------------------------------------------------------------------------
// Exclusive scan (3-phase, blocks of 1024)
// ---------------------------------------------------------------------------
__global__ void scan_block(const int* __restrict__ in, int* __restrict__ out,
                           int* __restrict__ aux, int n) {
    __shared__ int sm[1024];
    const int tid = threadIdx.x;
    const int i = blockIdx.x * 1024 + tid;
    int v = (i < n) ? in[i] : 0;
    sm[tid] = v;
    __syncthreads();
#pragma unroll
    for (int o = 1; o < 1024; o <<= 1) {
        int t = (tid >= o) ? sm[tid - o] : 0;
        __syncthreads();
        sm[tid] += t;
        __syncthreads();
    }
    if (i < n) out[i] = sm[tid] - v;            // exclusive
    if (tid == 1023) aux[blockIdx.x] = sm[1023];
}

__global__ void scan_aux(int* __restrict__ aux, int nb) {
    if (threadIdx.x == 0 && blockIdx.x == 0) {
        int s = 0;
        for (int i = 0; i < nb; i++) { int t = aux[i]; aux[i] = s; s += t; }
    }
}

__global__ void scan_add(int* __restrict__ out, const int* __restrict__ aux,
                         int n, int total) {
    int i = blockIdx.x * 1024 + threadIdx.x;
    if (i < n) out[i] += aux[blockIdx.x];
    if (i == 0) out[n] = total;
}

// ---------------------------------------------------------------------------
// CSR fill (both directions in one pass)
// ---------------------------------------------------------------------------
__global__ void fill_csr(const int* __restrict__ nidx, const int* __restrict__ eidx,
                         int* __restrict__ cur_n, int* __restrict__ cur_e,
                         int* __restrict__ adj_n, int* __restrict__ adj_e, int n) {
    int i = blockIdx.x * blockDim.x + threadIdx.x;
    if (i < n) {
        int v = nidx[i], e = eidx[i];
        adj_n[atomicAdd(cur_n + v, 1)] = e;
        adj_e[atomicAdd(cur_e + e, 1)] = v;
    }
}

// ---------------------------------------------------------------------------
// Register-blocked GEMM: Y[N,F] (stride S) = X[N,K] @ W[K,F]
// blockDim = (F/4, RPB). Each thread computes a 4-col quad of one row.
// ---------------------------------------------------------------------------
template <int K, int F, int S, int RPB>
__global__ void gemm_kernel(const float* __restrict__ X,
                            const float* __restrict__ W,
                            float* __restrict__ Y, int N) {
    constexpr int XST = K + 4;                 // padded to dodge bank conflicts
    __shared__ float ws[K * F];
    __shared__ float xs[RPB * XST];
    const int tx = threadIdx.x;                // 0..F/4-1
    const int ty = threadIdx.y;                // 0..RPB-1
    const int tid = ty * (F / 4) + tx;
    const int nth = (F / 4) * RPB;

    for (int i = tid; i < K * F / 4; i += nth)
        ((float4*)ws)[i] = ((const float4*)W)[i];

    const int row0 = blockIdx.x * RPB;
    for (int i = tid; i < RPB * (K / 4); i += nth) {
        int r = i / (K / 4), c = i % (K / 4);
        float4 v = make_float4(0.f, 0.f, 0.f, 0.f);
        if (row0 + r < N) v = ((const float4*)X)[(size_t)(row0 + r) * (K / 4) + c];
        *(float4*)&xs[r * XST + c * 4] = v;
    }
    __syncthreads();

    float4 acc = make_float4(0.f, 0.f, 0.f, 0.f);
#pragma unroll
    for (int k = 0; k < K; k += 4) {
        float4 xv = *(const float4*)&xs[ty * XST + k];
        float4 w0 = *(const float4*)&ws[(k + 0) * F + tx * 4];
        float4 w1 = *(const float4*)&ws[(k + 1) * F + tx * 4];
        float4 w2 = *(const float4*)&ws[(k + 2) * F + tx * 4];
        float4 w3 = *(const float4*)&ws[(k + 3) * F + tx * 4];
        acc.x += xv.x * w0.x + xv.y * w1.x + xv.z * w2.x + xv.w * w3.x;
        acc.y += xv.x * w0.y + xv.y * w1.y + xv.z * w2.y + xv.w * w3.y;
        acc.z += xv.x * w0.z + xv.y * w1.z + xv.z * w2.z + xv.w * w3.z;
        acc.w += xv.x * w0.w + xv.y * w1.w + xv.z * w2.w + xv.w * w3.w;
    }
    const int row = row0 + ty;
    if (row < N) *(float4*)&Y[(size_t)row * S + tx * 4] = acc;
}

// ---------------------------------------------------------------------------
// CSR gather: one warp per destination row. Lane = feature column.
// MODE 0: dst = scale * sum                (edge aggregation)
// MODE 1: dst = relu(scale * sum + bias)   (layer-1 node aggregation, LF=32)
// MODE 2: dst = log_softmax(scale*sum+bias) (layer-2 node aggregation, LF=40)
// ---------------------------------------------------------------------------
template <int SS, int DS, int LF, int MODE>
__global__ void gather_kernel(const int* __restrict__ off,
                              const int* __restrict__ adj,
                              const float* __restrict__ src,
                              const float* __restrict__ scale,
                              const float* __restrict__ bias,
                              float* __restrict__ dst, int nrows) {
    const int row  = (blockIdx.x * blockDim.x + threadIdx.x) >> 5;
    const int lane = threadIdx.x & 31;
    if (row >= nrows) return;

    const int s = off[row], e = off[row + 1];
    float a0 = 0.f, a1 = 0.f;
    int j = s;
    for (; j + 4 <= e; j += 4) {
        int m0 = adj[j], m1 = adj[j + 1], m2 = adj[j + 2], m3 = adj[j + 3];
        const float* r0 = src + (size_t)m0 * SS;
        const float* r1 = src + (size_t)m1 * SS;
        const float* r2 = src + (size_t)m2 * SS;
        const float* r3 = src + (size_t)m3 * SS;
        a0 += r0[lane]; a0 += r1[lane]; a0 += r2[lane]; a0 += r3[lane];
        if (LF > 32 && lane < LF - 32) {
            a1 += r0[lane + 32]; a1 += r1[lane + 32];
            a1 += r2[lane + 32]; a1 += r3[lane + 32];
        }
    }
    for (; j < e; ++j) {
        int m = adj[j];
        const float* r = src + (size_t)m * SS;
        a0 += r[lane];
        if (LF > 32 && lane < LF - 32) a1 += r[lane + 32];
    }

    const float f = scale[row];
    if (MODE == 0) {
        dst[(size_t)row * DS + lane] = a0 * f;
        if (LF > 32 && lane < LF - 32) dst[(size_t)row * DS + lane + 32] = a1 * f;
    } else if (MODE == 1) {
        float z = a0 * f + bias[lane];
        dst[(size_t)row * DS + lane] = fmaxf(z, 0.f);
    } else {
        float z0 = a0 * f + bias[lane];
        float z1 = (lane < LF - 32) ? (a1 * f + bias[lane + 32]) : -1e30f;
        float m = fmaxf(z0, z1);
#pragma unroll
        for (int o = 16; o; o >>= 1) m = fmaxf(m, __shfl_xor_sync(0xffffffffu, m, o));
        float ex = __expf(z0 - m) + ((lane < LF - 32) ? __expf(z1 - m) : 0.f);
#pragma unroll
        for (int o = 16; o; o >>= 1) ex += __shfl_xor_sync(0xffffffffu, ex, o);
        const float lse = __logf(ex) + m;
        dst[(size_t)row * DS + lane] = z0 - lse;
        if (lane < LF - 32) dst[(size_t)row * DS + lane + 32] = z1 - lse;
    }
}

// ---------------------------------------------------------------------------
// Launch
// ---------------------------------------------------------------------------
extern "C" void kernel_launch(void* const* d_in, const int* in_sizes, int n_in,
                              void* d_out, int out_size) {
    const float* x    = (const float*)d_in[0];
    const int*   nidx = (const int*)d_in[1];
    const int*   eidx = (const int*)d_in[2];
    const float* W1   = (const float*)d_in[3];
    const float* b1   = (const float*)d_in[4];
    const float* W2   = (const float*)d_in[5];
    const float* b2   = (const float*)d_in[6];
    float* out = (float*)d_out;

    float *xw, *ef, *h1, *dinv, *binv;
    int *cnt_n, *cnt_e, *off_n, *off_e, *cur_n, *cur_e, *adj_n, *adj_e, *aux_n, *aux_e;
    cudaGetSymbolAddress((void**)&xw,    g_xw);
    cudaGetSymbolAddress((void**)&ef,    g_ef);
    cudaGetSymbolAddress((void**)&h1,    g_h1);
    cudaGetSymbolAddress((void**)&dinv,  g_dinv);
    cudaGetSymbolAddress((void**)&binv,  g_binv);
    cudaGetSymbolAddress((void**)&cnt_n, g_cnt_n);
    cudaGetSymbolAddress((void**)&cnt_e, g_cnt_e);
    cudaGetSymbolAddress((void**)&off_n, g_off_n);
    cudaGetSymbolAddress((void**)&off_e, g_off_e);
    cudaGetSymbolAddress((void**)&cur_n, g_cur_n);
    cudaGetSymbolAddress((void**)&cur_e, g_cur_e);
    cudaGetSymbolAddress((void**)&adj_n, g_adj_n);
    cudaGetSymbolAddress((void**)&adj_e, g_adj_e);
    cudaGetSymbolAddress((void**)&aux_n, g_aux_n);
    cudaGetSymbolAddress((void**)&aux_e, g_aux_e);

    const int nb_n = (N_NODES + 1023) / 1024;   // 98
    const int nb_e = (N_EDGES + 1023) / 1024;   // 49

    // ---- degrees + inverse degrees ----
    cudaMemsetAsync(cnt_n, 0, N_NODES * sizeof(int));
    cudaMemsetAsync(cnt_e, 0, N_EDGES * sizeof(int));
    degree_kernel<<<(N_INC + 255) / 256, 256>>>(nidx, eidx, cnt_n, cnt_e, N_INC);
    invert_kernel<<<(N_NODES + 255) / 256, 256>>>(cnt_n, dinv, N_NODES);
    invert_kernel<<<(N_EDGES + 255) / 256, 256>>>(cnt_e, binv, N_EDGES);

    // ---- CSR build (both directions) ----
    scan_block<<<nb_n, 1024>>>(cnt_n, off_n, aux_n, N_NODES);
    scan_aux<<<1, 32>>>(aux_n, nb_n);
    scan_add<<<nb_n, 1024>>>(off_n, aux_n, N_NODES, N_INC);
    scan_block<<<nb_e, 1024>>>(cnt_e, off_e, aux_e, N_EDGES);
    scan_aux<<<1, 32>>>(aux_e, nb_e);
    scan_add<<<nb_e, 1024>>>(off_e, aux_e, N_EDGES, N_INC);
    cudaMemcpyAsync(cur_n, off_n, N_NODES * sizeof(int), cudaMemcpyDeviceToDevice);
    cudaMemcpyAsync(cur_e, off_e, N_EDGES * sizeof(int), cudaMemcpyDeviceToDevice);
    fill_csr<<<(N_INC + 255) / 256, 256>>>(nidx, eidx, cur_n, cur_e, adj_n, adj_e, N_INC);

    // ---- layer 1 ----
    gemm_kernel<D_IN, D_HID, D_HID, 32>
        <<<(N_NODES + 31) / 32, dim3(D_HID / 4, 32)>>>(x, W1, xw, N_NODES);
    gather_kernel<D_HID, D_HID, D_HID, 0>
        <<<(N_EDGES + 7) / 8, 256>>>(off_e, adj_e, xw, binv, nullptr, ef, N_EDGES);
    gather_kernel<D_HID, D_HID, D_HID, 1>
        <<<(N_NODES + 7) / 8, 256>>>(off_n, adj_n, ef, dinv, b1, h1, N_NODES);

    // ---- layer 2 ----
    gemm_kernel<D_HID, N_CLASSES, S2, 32>
        <<<(N_NODES + 31) / 32, dim3(N_CLASSES / 4, 32)>>>(h1, W2, xw, N_NODES);
    gather_kernel<S2, S2, N_CLASSES, 0>
        <<<(N_EDGES + 7) / 8, 256>>>(off_e, adj_e, xw, binv, nullptr, ef, N_EDGES);
    gather_kernel<S2, N_CLASSES, N_CLASSES, 2>
        <<<(N_NODES + 7) / 8, 256>>>(off_n, adj_n, ef, dinv, b2, out, N_NODES);
}

// round 4
// speedup vs baseline: 1.3787x; 1.0562x over previous
#include <cuda_runtime.h>
#include <cstddef>

#define N_NODES   100000
#define N_EDGES   50000
#define N_INC     3200000
#define D_IN      128
#define D_HID     32
#define N_CLASSES 40

// ---------------------------------------------------------------------------
// Scratch (static device globals)
// ---------------------------------------------------------------------------
__device__ float g_xw[(size_t)N_NODES * D_HID];  // X@W1
__device__ float g_ef[(size_t)N_EDGES * D_HID];  // hyperedge features (32-wide both layers)
__device__ float g_h1[(size_t)N_NODES * D_HID];  // hidden layer
__device__ float g_dinv[N_NODES];
__device__ float g_binv[N_EDGES];

__device__ int g_cnt_n[N_NODES];
__device__ int g_cnt_e[N_EDGES];
__device__ int g_off_n[N_NODES + 1];
__device__ int g_off_e[N_EDGES + 1];
__device__ int g_cur_n[N_NODES];
__device__ int g_cur_e[N_EDGES];
__device__ int g_adj_n[N_INC];   // edge ids grouped by node
__device__ int g_adj_e[N_INC];   // node ids grouped by edge
__device__ int g_aux_n[128];
__device__ int g_aux_e[128];

// ---------------------------------------------------------------------------
// Degree counting + fused inverse for both tables
// ---------------------------------------------------------------------------
__global__ void degree_kernel(const int* __restrict__ nidx,
                              const int* __restrict__ eidx,
                              int* __restrict__ cn, int* __restrict__ ce, int n) {
    int i = blockIdx.x * blockDim.x + threadIdx.x;
    if (i < n) {
        atomicAdd(cn + nidx[i], 1);
        atomicAdd(ce + eidx[i], 1);
    }
}

__global__ void invert_kernel(const int* __restrict__ cn, float* __restrict__ dn,
                              const int* __restrict__ ce, float* __restrict__ de) {
    int i = blockIdx.x * blockDim.x + threadIdx.x;
    if (i < N_NODES) {
        int d = cn[i];
        dn[i] = (d > 0) ? (1.0f / (float)d) : 0.0f;
    }
    if (i < N_EDGES) {
        int d = ce[i];
        de[i] = (d > 0) ? (1.0f / (float)d) : 0.0f;
    }
}

// ---------------------------------------------------------------------------
// Exclusive scan (3-phase, blocks of 1024)
// ---------------------------------------------------------------------------
__global__ void scan_block(const int* __restrict__ in, int* __restrict__ out,
                           int* __restrict__ aux, int n) {
    __shared__ int sm[1024];
    const int tid = threadIdx.x;
    const int i = blockIdx.x * 1024 + tid;
    int v = (i < n) ? in[i] : 0;
    sm[tid] = v;
    __syncthreads();
#pragma unroll
    for (int o = 1; o < 1024; o <<= 1) {
        int t = (tid >= o) ? sm[tid - o] : 0;
        __syncthreads();
        sm[tid] += t;
        __syncthreads();
    }
    if (i < n) out[i] = sm[tid] - v;            // exclusive
    if (tid == 1023) aux[blockIdx.x] = sm[1023];
}

__global__ void scan_aux(int* __restrict__ aux, int nb) {
    if (threadIdx.x == 0 && blockIdx.x == 0) {
        int s = 0;
        for (int i = 0; i < nb; i++) { int t = aux[i]; aux[i] = s; s += t; }
    }
}

__global__ void scan_add(int* __restrict__ out, const int* __restrict__ aux,
                         int n, int total) {
    int i = blockIdx.x * 1024 + threadIdx.x;
    if (i < n) out[i] += aux[blockIdx.x];
    if (i == 0) out[n] = total;
}

// ---------------------------------------------------------------------------
// CSR fill (both directions in one pass)
// ---------------------------------------------------------------------------
__global__ void fill_csr(const int* __restrict__ nidx, const int* __restrict__ eidx,
                         int* __restrict__ cur_n, int* __restrict__ cur_e,
                         int* __restrict__ adj_n, int* __restrict__ adj_e, int n) {
    int i = blockIdx.x * blockDim.x + threadIdx.x;
    if (i < n) {
        int v = nidx[i], e = eidx[i];
        adj_n[atomicAdd(cur_n + v, 1)] = e;
        adj_e[atomicAdd(cur_e + e, 1)] = v;
    }
}

// ---------------------------------------------------------------------------
// GEMM1: Y[N,32] = X[N,128] @ W[128,32]. Register tile: 4 rows x 4 cols/thread.
// blockDim (8, 8) = 64 threads; block covers 32 rows. smem = 16KB + ~17KB.
// ---------------------------------------------------------------------------
#define G_RPB 32
__global__ void gemm1_kernel(const float* __restrict__ X,
                             const float* __restrict__ W,
                             float* __restrict__ Y, int N) {
    constexpr int K = D_IN, F = D_HID;
    constexpr int XST = K + 4;
    __shared__ float ws[K * F];                 // 16 KB
    __shared__ float xs[G_RPB * XST];           // ~16.9 KB
    const int tx = threadIdx.x;                 // 0..7  (col quad)
    const int ty = threadIdx.y;                 // 0..7  (row group of 4)
    const int tid = ty * 8 + tx;

    for (int i = tid; i < K * F / 4; i += 64)
        ((float4*)ws)[i] = ((const float4*)W)[i];

    const int row0 = blockIdx.x * G_RPB;
    for (int i = tid; i < G_RPB * (K / 4); i += 64) {
        int r = i / (K / 4), c = i % (K / 4);
        float4 v = make_float4(0.f, 0.f, 0.f, 0.f);
        if (row0 + r < N) v = ((const float4*)X)[(size_t)(row0 + r) * (K / 4) + c];
        *(float4*)&xs[r * XST + c * 4] = v;
    }
    __syncthreads();

    float4 acc[4];
#pragma unroll
    for (int r = 0; r < 4; r++) acc[r] = make_float4(0.f, 0.f, 0.f, 0.f);

#pragma unroll
    for (int k = 0; k < K; k += 4) {
        float4 w0 = *(const float4*)&ws[(k + 0) * F + tx * 4];
        float4 w1 = *(const float4*)&ws[(k + 1) * F + tx * 4];
        float4 w2 = *(const float4*)&ws[(k + 2) * F + tx * 4];
        float4 w3 = *(const float4*)&ws[(k + 3) * F + tx * 4];
#pragma unroll
        for (int r = 0; r < 4; r++) {
            float4 xv = *(const float4*)&xs[(ty * 4 + r) * XST + k];
            acc[r].x += xv.x * w0.x + xv.y * w1.x + xv.z * w2.x + xv.w * w3.x;
            acc[r].y += xv.x * w0.y + xv.y * w1.y + xv.z * w2.y + xv.w * w3.y;
            acc[r].z += xv.x * w0.z + xv.y * w1.z + xv.z * w2.z + xv.w * w3.z;
            acc[r].w += xv.x * w0.w + xv.y * w1.w + xv.z * w2.w + xv.w * w3.w;
        }
    }
#pragma unroll
    for (int r = 0; r < 4; r++) {
        const int row = row0 + ty * 4 + r;
        if (row < N) *(float4*)&Y[(size_t)row * F + tx * 4] = acc[r];
    }
}

// ---------------------------------------------------------------------------
// CSR gather, 32-wide rows, one warp per destination row, lane = column.
// MODE 0: dst = scale * sum
// MODE 1: dst = relu(scale * sum + bias)
// ---------------------------------------------------------------------------
template <int MODE>
__global__ void gather_kernel(const int* __restrict__ off,
                              const int* __restrict__ adj,
                              const float* __restrict__ src,
                              const float* __restrict__ scale,
                              const float* __restrict__ bias,
                              float* __restrict__ dst, int nrows) {
    const int row  = (blockIdx.x * blockDim.x + threadIdx.x) >> 5;
    const int lane = threadIdx.x & 31;
    if (row >= nrows) return;

    const int s = off[row], e = off[row + 1];
    float a = 0.f;
    int j = s;
    for (; j + 8 <= e; j += 8) {
        int m0 = adj[j],     m1 = adj[j + 1], m2 = adj[j + 2], m3 = adj[j + 3];
        int m4 = adj[j + 4], m5 = adj[j + 5], m6 = adj[j + 6], m7 = adj[j + 7];
        float v0 = src[(size_t)m0 * D_HID + lane];
        float v1 = src[(size_t)m1 * D_HID + lane];
        float v2 = src[(size_t)m2 * D_HID + lane];
        float v3 = src[(size_t)m3 * D_HID + lane];
        float v4 = src[(size_t)m4 * D_HID + lane];
        float v5 = src[(size_t)m5 * D_HID + lane];
        float v6 = src[(size_t)m6 * D_HID + lane];
        float v7 = src[(size_t)m7 * D_HID + lane];
        a += ((v0 + v1) + (v2 + v3)) + ((v4 + v5) + (v6 + v7));
    }
    for (; j < e; ++j)
        a += src[(size_t)adj[j] * D_HID + lane];

    const float f = scale[row];
    if (MODE == 0) {
        dst[(size_t)row * D_HID + lane] = a * f;
    } else {
        float z = a * f + bias[lane];
        dst[(size_t)row * D_HID + lane] = fmaxf(z, 0.f);
    }
}

// ---------------------------------------------------------------------------
// Fused final: node-gather (32-wide) + @W2 [32,40] + b2 + log_softmax.
// One warp per node; logits via shfl-broadcast against smem W2.
// ---------------------------------------------------------------------------
__global__ void gather_w2_logsoftmax(const int* __restrict__ off,
                                     const int* __restrict__ adj,
                                     const float* __restrict__ src,
                                     const float* __restrict__ dinv,
                                     const float* __restrict__ W2,
                                     const float* __restrict__ b2,
                                     float* __restrict__ out, int nrows) {
    __shared__ float w2s[D_HID * N_CLASSES];   // 5 KB
    __shared__ float b2s[N_CLASSES];
    {
        const int t = threadIdx.x;
        for (int i = t; i < D_HID * N_CLASSES; i += blockDim.x) w2s[i] = W2[i];
        if (t < N_CLASSES) b2s[t] = b2[t];
    }
    __syncthreads();

    const int row  = (blockIdx.x * blockDim.x + threadIdx.x) >> 5;
    const int lane = threadIdx.x & 31;
    if (row >= nrows) return;

    const int s = off[row], e = off[row + 1];
    float a = 0.f;
    int j = s;
    for (; j + 8 <= e; j += 8) {
        int m0 = adj[j],     m1 = adj[j + 1], m2 = adj[j + 2], m3 = adj[j + 3];
        int m4 = adj[j + 4], m5 = adj[j + 5], m6 = adj[j + 6], m7 = adj[j + 7];
        float v0 = src[(size_t)m0 * D_HID + lane];
        float v1 = src[(size_t)m1 * D_HID + lane];
        float v2 = src[(size_t)m2 * D_HID + lane];
        float v3 = src[(size_t)m3 * D_HID + lane];
        float v4 = src[(size_t)m4 * D_HID + lane];
        float v5 = src[(size_t)m5 * D_HID + lane];
        float v6 = src[(size_t)m6 * D_HID + lane];
        float v7 = src[(size_t)m7 * D_HID + lane];
        a += ((v0 + v1) + (v2 + v3)) + ((v4 + v5) + (v6 + v7));
    }
    for (; j < e; ++j)
        a += src[(size_t)adj[j] * D_HID + lane];

    a *= dinv[row];                            // aggregated hidden feature, lane = k

    // logits: z[c] = sum_k a_k * W2[k][c] + b2[c]; lane c, lanes 0..7 also c+32
    float z0 = 0.f, z1 = 0.f;
#pragma unroll
    for (int k = 0; k < D_HID; k++) {
        float ak = __shfl_sync(0xffffffffu, a, k);
        z0 += ak * w2s[k * N_CLASSES + lane];
        if (lane < N_CLASSES - 32) z1 += ak * w2s[k * N_CLASSES + 32 + lane];
    }
    z0 += b2s[lane];
    z1 = (lane < N_CLASSES - 32) ? (z1 + b2s[32 + lane]) : -1e30f;

    float m = fmaxf(z0, z1);
#pragma unroll
    for (int o = 16; o; o >>= 1) m = fmaxf(m, __shfl_xor_sync(0xffffffffu, m, o));
    float ex = __expf(z0 - m) + ((lane < N_CLASSES - 32) ? __expf(z1 - m) : 0.f);
#pragma unroll
    for (int o = 16; o; o >>= 1) ex += __shfl_xor_sync(0xffffffffu, ex, o);
    const float lse = __logf(ex) + m;

    out[(size_t)row * N_CLASSES + lane] = z0 - lse;
    if (lane < N_CLASSES - 32)
        out[(size_t)row * N_CLASSES + 32 + lane] = z1 - lse;
}

// ---------------------------------------------------------------------------
// Launch
// ---------------------------------------------------------------------------
extern "C" void kernel_launch(void* const* d_in, const int* in_sizes, int n_in,
                              void* d_out, int out_size) {
    const float* x    = (const float*)d_in[0];
    const int*   nidx = (const int*)d_in[1];
    const int*   eidx = (const int*)d_in[2];
    const float* W1   = (const float*)d_in[3];
    const float* b1   = (const float*)d_in[4];
    const float* W2   = (const float*)d_in[5];
    const float* b2   = (const float*)d_in[6];
    float* out = (float*)d_out;

    float *xw, *ef, *h1, *dinv, *binv;
    int *cnt_n, *cnt_e, *off_n, *off_e, *cur_n, *cur_e, *adj_n, *adj_e, *aux_n, *aux_e;
    cudaGetSymbolAddress((void**)&xw,    g_xw);
    cudaGetSymbolAddress((void**)&ef,    g_ef);
    cudaGetSymbolAddress((void**)&h1,    g_h1);
    cudaGetSymbolAddress((void**)&dinv,  g_dinv);
    cudaGetSymbolAddress((void**)&binv,  g_binv);
    cudaGetSymbolAddress((void**)&cnt_n, g_cnt_n);
    cudaGetSymbolAddress((void**)&cnt_e, g_cnt_e);
    cudaGetSymbolAddress((void**)&off_n, g_off_n);
    cudaGetSymbolAddress((void**)&off_e, g_off_e);
    cudaGetSymbolAddress((void**)&cur_n, g_cur_n);
    cudaGetSymbolAddress((void**)&cur_e, g_cur_e);
    cudaGetSymbolAddress((void**)&adj_n, g_adj_n);
    cudaGetSymbolAddress((void**)&adj_e, g_adj_e);
    cudaGetSymbolAddress((void**)&aux_n, g_aux_n);
    cudaGetSymbolAddress((void**)&aux_e, g_aux_e);

    const int nb_n = (N_NODES + 1023) / 1024;   // 98
    const int nb_e = (N_EDGES + 1023) / 1024;   // 49

    // ---- degrees + inverse degrees ----
    cudaMemsetAsync(cnt_n, 0, N_NODES * sizeof(int));
    cudaMemsetAsync(cnt_e, 0, N_EDGES * sizeof(int));
    degree_kernel<<<(N_INC + 255) / 256, 256>>>(nidx, eidx, cnt_n, cnt_e, N_INC);
    invert_kernel<<<(N_NODES + 255) / 256, 256>>>(cnt_n, dinv, cnt_e, binv);

    // ---- CSR build (both directions) ----
    scan_block<<<nb_n, 1024>>>(cnt_n, off_n, aux_n, N_NODES);
    scan_aux<<<1, 32>>>(aux_n, nb_n);
    scan_add<<<nb_n, 1024>>>(off_n, aux_n, N_NODES, N_INC);
    scan_block<<<nb_e, 1024>>>(cnt_e, off_e, aux_e, N_EDGES);
    scan_aux<<<1, 32>>>(aux_e, nb_e);
    scan_add<<<nb_e, 1024>>>(off_e, aux_e, N_EDGES, N_INC);
    cudaMemcpyAsync(cur_n, off_n, N_NODES * sizeof(int), cudaMemcpyDeviceToDevice);
    cudaMemcpyAsync(cur_e, off_e, N_EDGES * sizeof(int), cudaMemcpyDeviceToDevice);
    fill_csr<<<(N_INC + 255) / 256, 256>>>(nidx, eidx, cur_n, cur_e, adj_n, adj_e, N_INC);

    // ---- layer 1: h1 = relu(Dinv H Binv H^T (x W1) + b1) ----
    gemm1_kernel<<<(N_NODES + G_RPB - 1) / G_RPB, dim3(8, 8)>>>(x, W1, xw, N_NODES);
    gather_kernel<0><<<(N_EDGES + 7) / 8, 256>>>(off_e, adj_e, xw, binv, nullptr, ef, N_EDGES);
    gather_kernel<1><<<(N_NODES + 7) / 8, 256>>>(off_n, adj_n, ef, dinv, b1, h1, N_NODES);

    // ---- layer 2 (aggregate in hidden space; W2 applied post-aggregation) ----
    gather_kernel<0><<<(N_EDGES + 7) / 8, 256>>>(off_e, adj_e, h1, binv, nullptr, ef, N_EDGES);
    gather_w2_logsoftmax<<<(N_NODES + 7) / 8, 256>>>(off_n, adj_n, ef, dinv, W2, b2, out, N_NODES);
}

// round 6
// speedup vs baseline: 1.5862x; 1.1505x over previous
#include <cuda_runtime.h>
#include <cstddef>

#define N_NODES   100000
#define N_EDGES   50000
#define N_INC     3200000
#define D_IN      128
#define D_HID     32
#define N_CLASSES 40

// ---------------------------------------------------------------------------
// Scratch (static device globals)
// ---------------------------------------------------------------------------
__device__ float g_xw[(size_t)N_NODES * D_HID];  // X@W1
__device__ float g_ef[(size_t)N_EDGES * D_HID];  // hyperedge features
__device__ float g_h1[(size_t)N_NODES * D_HID];  // hidden layer
__device__ float g_dinv[N_NODES];
__device__ float g_binv[N_EDGES];

__device__ int g_cnt_n[N_NODES];
__device__ int g_cnt_e[N_EDGES];
__device__ int g_off_n[N_NODES + 1];
__device__ int g_off_e[N_EDGES + 1];
__device__ int g_cur_n[N_NODES];
__device__ int g_cur_e[N_EDGES];
__device__ int g_adj_n[N_INC];   // edge ids grouped by node
__device__ int g_adj_e[N_INC];   // node ids grouped by edge
__device__ int g_aux_n[128];
__device__ int g_aux_e[128];

#define NB_N ((N_NODES + 1023) / 1024)   // 98
#define NB_E ((N_EDGES + 1023) / 1024)   // 49

// ---------------------------------------------------------------------------
// Degree counting
// ---------------------------------------------------------------------------
__global__ void degree_kernel(const int* __restrict__ nidx,
                              const int* __restrict__ eidx,
                              int* __restrict__ cn, int* __restrict__ ce, int n) {
    int i = blockIdx.x * blockDim.x + threadIdx.x;
    if (i < n) {
        atomicAdd(cn + nidx[i], 1);
        atomicAdd(ce + eidx[i], 1);
    }
}

// ---------------------------------------------------------------------------
// Combined block scan (node + edge arrays in one grid) + fused 1/deg
// ---------------------------------------------------------------------------
__global__ void scan_block2(const int* __restrict__ cnt_n, int* __restrict__ off_n,
                            int* __restrict__ aux_n, float* __restrict__ dinv,
                            const int* __restrict__ cnt_e, int* __restrict__ off_e,
                            int* __restrict__ aux_e, float* __restrict__ binv) {
    __shared__ int sm[1024];
    const int b = blockIdx.x;
    const int* in;  int* out; int* aux; float* inv; int n; int bb;
    if (b < NB_N) { in = cnt_n; out = off_n; aux = aux_n; inv = dinv; n = N_NODES; bb = b; }
    else          { in = cnt_e; out = off_e; aux = aux_e; inv = binv; n = N_EDGES; bb = b - NB_N; }

    const int tid = threadIdx.x;
    const int i = bb * 1024 + tid;
    int v = (i < n) ? in[i] : 0;
    if (i < n) inv[i] = (v > 0) ? (1.0f / (float)v) : 0.0f;
    sm[tid] = v;
    __syncthreads();
#pragma unroll
    for (int o = 1; o < 1024; o <<= 1) {
        int t = (tid >= o) ? sm[tid - o] : 0;
        __syncthreads();
        sm[tid] += t;
        __syncthreads();
    }
    if (i < n) out[i] = sm[tid] - v;            // exclusive
    if (tid == 1023) aux[bb] = sm[1023];
}

// Parallel aux scan (both arrays) — 1 block, 128 threads.
__global__ void scan_aux2(int* __restrict__ aux_n, int* __restrict__ aux_e) {
    __shared__ int sm[128];
    const int t = threadIdx.x;

    int orig = (t < NB_N) ? aux_n[t] : 0;
    sm[t] = orig;
    __syncthreads();
#pragma unroll
    for (int o = 1; o < 128; o <<= 1) {
        int v = (t >= o) ? sm[t - o] : 0;
        __syncthreads();
        sm[t] += v;
        __syncthreads();
    }
    if (t < NB_N) aux_n[t] = sm[t] - orig;
    __syncthreads();

    orig = (t < NB_E) ? aux_e[t] : 0;
    sm[t] = orig;
    __syncthreads();
#pragma unroll
    for (int o = 1; o < 128; o <<= 1) {
        int v = (t >= o) ? sm[t - o] : 0;
        __syncthreads();
        sm[t] += v;
        __syncthreads();
    }
    if (t < NB_E) aux_e[t] = sm[t] - orig;
}

// Combined add-pass; also initializes cursors and off[n] sentinel.
__global__ void scan_add2(int* __restrict__ off_n, const int* __restrict__ aux_n,
                          int* __restrict__ cur_n,
                          int* __restrict__ off_e, const int* __restrict__ aux_e,
                          int* __restrict__ cur_e) {
    const int b = blockIdx.x;
    if (b < NB_N) {
        int i = b * 1024 + threadIdx.x;
        if (i < N_NODES) {
            int v = off_n[i] + aux_n[b];
            off_n[i] = v; cur_n[i] = v;
        }
        if (i == 0) off_n[N_NODES] = N_INC;
    } else {
        int i = (b - NB_N) * 1024 + threadIdx.x;
        if (i < N_EDGES) {
            int v = off_e[i] + aux_e[b - NB_N];
            off_e[i] = v; cur_e[i] = v;
        }
        if (i == 0) off_e[N_EDGES] = N_INC;
    }
}

// ---------------------------------------------------------------------------
// CSR fill (both directions in one pass)
// ---------------------------------------------------------------------------
__global__ void fill_csr(const int* __restrict__ nidx, const int* __restrict__ eidx,
                         int* __restrict__ cur_n, int* __restrict__ cur_e,
                         int* __restrict__ adj_n, int* __restrict__ adj_e, int n) {
    int i = blockIdx.x * blockDim.x + threadIdx.x;
    if (i < n) {
        int v = nidx[i], e = eidx[i];
        adj_n[atomicAdd(cur_n + v, 1)] = e;
        adj_e[atomicAdd(cur_e + e, 1)] = v;
    }
}

// ---------------------------------------------------------------------------
// GEMM1: Y[N,32] = X[N,128] @ W[128,32]. 4x4 register tile per thread.
// blockDim (8,8)=64 threads; block covers 32 rows. smem ~33 KB.
// ---------------------------------------------------------------------------
#define G_RPB 32
__global__ void gemm1_kernel(const float* __restrict__ X,
                             const float* __restrict__ W,
                             float* __restrict__ Y, int N) {
    constexpr int K = D_IN, F = D_HID;
    constexpr int XST = K + 4;
    __shared__ float ws[K * F];
    __shared__ float xs[G_RPB * XST];
    const int tx = threadIdx.x;
    const int ty = threadIdx.y;
    const int tid = ty * 8 + tx;

    for (int i = tid; i < K * F / 4; i += 64)
        ((float4*)ws)[i] = ((const float4*)W)[i];

    const int row0 = blockIdx.x * G_RPB;
    for (int i = tid; i < G_RPB * (K / 4); i += 64) {
        int r = i / (K / 4), c = i % (K / 4);
        float4 v = make_float4(0.f, 0.f, 0.f, 0.f);
        if (row0 + r < N) v = ((const float4*)X)[(size_t)(row0 + r) * (K / 4) + c];
        *(float4*)&xs[r * XST + c * 4] = v;
    }
    __syncthreads();

    float4 acc[4];
#pragma unroll
    for (int r = 0; r < 4; r++) acc[r] = make_float4(0.f, 0.f, 0.f, 0.f);

#pragma unroll
    for (int k = 0; k < K; k += 4) {
        float4 w0 = *(const float4*)&ws[(k + 0) * F + tx * 4];
        float4 w1 = *(const float4*)&ws[(k + 1) * F + tx * 4];
        float4 w2 = *(const float4*)&ws[(k + 2) * F + tx * 4];
        float4 w3 = *(const float4*)&ws[(k + 3) * F + tx * 4];
#pragma unroll
        for (int r = 0; r < 4; r++) {
            float4 xv = *(const float4*)&xs[(ty * 4 + r) * XST + k];
            acc[r].x += xv.x * w0.x + xv.y * w1.x + xv.z * w2.x + xv.w * w3.x;
            acc[r].y += xv.x * w0.y + xv.y * w1.y + xv.z * w2.y + xv.w * w3.y;
            acc[r].z += xv.x * w0.z + xv.y * w1.z + xv.z * w2.z + xv.w * w3.z;
            acc[r].w += xv.x * w0.w + xv.y * w1.w + xv.z * w2.w + xv.w * w3.w;
        }
    }
#pragma unroll
    for (int r = 0; r < 4; r++) {
        const int row = row0 + ty * 4 + r;
        if (row < N) *(float4*)&Y[(size_t)row * F + tx * 4] = acc[r];
    }
}

// ---------------------------------------------------------------------------
// float4 CSR gather: warp per dst row; lane = (sub-row r = lane/8, quad q = lane%8).
// Each lane loads float4 -> one LDG.128 covers 4 member rows.
// Cross-sub-row reduction via shfl_xor(8),(16).
// MODE 0: dst = scale*sum   MODE 1: dst = relu(scale*sum + bias)
// ---------------------------------------------------------------------------
template <int MODE>
__global__ void gather_kernel(const int* __restrict__ off,
                              const int* __restrict__ adj,
                              const float* __restrict__ src,
                              const float* __restrict__ scale,
                              const float* __restrict__ bias,
                              float* __restrict__ dst, int nrows) {
    const int row  = (blockIdx.x * blockDim.x + threadIdx.x) >> 5;
    const int lane = threadIdx.x & 31;
    if (row >= nrows) return;
    const int r = lane >> 3;          // 0..3 sub-row slot
    const int q = lane & 7;           // 0..7 quad

    const int s = off[row], e = off[row + 1];
    float4 a = make_float4(0.f, 0.f, 0.f, 0.f);
    int j = s;
    for (; j + 8 <= e; j += 8) {
        int m0 = adj[j + r];
        int m1 = adj[j + 4 + r];
        float4 v0 = *(const float4*)(src + (size_t)m0 * D_HID + q * 4);
        float4 v1 = *(const float4*)(src + (size_t)m1 * D_HID + q * 4);
        a.x += v0.x + v1.x; a.y += v0.y + v1.y;
        a.z += v0.z + v1.z; a.w += v0.w + v1.w;
    }
    for (; j < e; j += 4) {
        if (j + r < e) {
            int m = adj[j + r];
            float4 v = *(const float4*)(src + (size_t)m * D_HID + q * 4);
            a.x += v.x; a.y += v.y; a.z += v.z; a.w += v.w;
        }
    }
#pragma unroll
    for (int o = 8; o <= 16; o <<= 1) {
        a.x += __shfl_xor_sync(0xffffffffu, a.x, o);
        a.y += __shfl_xor_sync(0xffffffffu, a.y, o);
        a.z += __shfl_xor_sync(0xffffffffu, a.z, o);
        a.w += __shfl_xor_sync(0xffffffffu, a.w, o);
    }

    if (r == 0) {
        const float f = scale[row];
        if (MODE == 0) {
            a.x *= f; a.y *= f; a.z *= f; a.w *= f;
        } else {
            float4 bb = *(const float4*)(bias + q * 4);
            a.x = fmaxf(a.x * f + bb.x, 0.f);
            a.y = fmaxf(a.y * f + bb.y, 0.f);
            a.z = fmaxf(a.z * f + bb.z, 0.f);
            a.w = fmaxf(a.w * f + bb.w, 0.f);
        }
        *(float4*)(dst + (size_t)row * D_HID + q * 4) = a;
    }
}

// ---------------------------------------------------------------------------
// Fused final: float4 node-gather + @W2 [32,40] + b2 + log_softmax.
// ---------------------------------------------------------------------------
__global__ void gather_w2_logsoftmax(const int* __restrict__ off,
                                     const int* __restrict__ adj,
                                     const float* __restrict__ src,
                                     const float* __restrict__ dinv,
                                     const float* __restrict__ W2,
                                     const float* __restrict__ b2,
                                     float* __restrict__ out, int nrows) {
    __shared__ float w2s[D_HID * N_CLASSES];
    __shared__ float b2s[N_CLASSES];
    {
        const int t = threadIdx.x;
        for (int i = t; i < D_HID * N_CLASSES; i += blockDim.x) w2s[i] = W2[i];
        if (t < N_CLASSES) b2s[t] = b2[t];
    }
    __syncthreads();

    const int row  = (blockIdx.x * blockDim.x + threadIdx.x) >> 5;
    const int lane = threadIdx.x & 31;
    if (row >= nrows) return;
    const int r = lane >> 3;
    const int q = lane & 7;

    const int s = off[row], e = off[row + 1];
    float4 a = make_float4(0.f, 0.f, 0.f, 0.f);
    int j = s;
    for (; j + 8 <= e; j += 8) {
        int m0 = adj[j + r];
        int m1 = adj[j + 4 + r];
        float4 v0 = *(const float4*)(src + (size_t)m0 * D_HID + q * 4);
        float4 v1 = *(const float4*)(src + (size_t)m1 * D_HID + q * 4);
        a.x += v0.x + v1.x; a.y += v0.y + v1.y;
        a.z += v0.z + v1.z; a.w += v0.w + v1.w;
    }
    for (; j < e; j += 4) {
        if (j + r < e) {
            int m = adj[j + r];
            float4 v = *(const float4*)(src + (size_t)m * D_HID + q * 4);
            a.x += v.x; a.y += v.y; a.z += v.z; a.w += v.w;
        }
    }
#pragma unroll
    for (int o = 8; o <= 16; o <<= 1) {
        a.x += __shfl_xor_sync(0xffffffffu, a.x, o);
        a.y += __shfl_xor_sync(0xffffffffu, a.y, o);
        a.z += __shfl_xor_sync(0xffffffffu, a.z, o);
        a.w += __shfl_xor_sync(0xffffffffu, a.w, o);
    }

    const float di = dinv[row];
    a.x *= di; a.y *= di; a.z *= di; a.w *= di;
    // feature k lives on lanes with q == k>>2 (all r replicas agree), comp k&3.

    float z0 = 0.f, z1 = 0.f;
#pragma unroll
    for (int k = 0; k < D_HID; k++) {
        float comp = ((k & 3) == 0) ? a.x : ((k & 3) == 1) ? a.y
                    : ((k & 3) == 2) ? a.z : a.w;
        float ak = __shfl_sync(0xffffffffu, comp, k >> 2);   // from lane q=k>>2 (r=0 replica)
        z0 += ak * w2s[k * N_CLASSES + lane];
        if (lane < N_CLASSES - 32) z1 += ak * w2s[k * N_CLASSES + 32 + lane];
    }
    z0 += b2s[lane];
    z1 = (lane < N_CLASSES - 32) ? (z1 + b2s[32 + lane]) : -1e30f;

    float m = fmaxf(z0, z1);
#pragma unroll
    for (int o = 16; o; o >>= 1) m = fmaxf(m, __shfl_xor_sync(0xffffffffu, m, o));
    float ex = __expf(z0 - m) + ((lane < N_CLASSES - 32) ? __expf(z1 - m) : 0.f);
#pragma unroll
    for (int o = 16; o; o >>= 1) ex += __shfl_xor_sync(0xffffffffu, ex, o);
    const float lse = __logf(ex) + m;

    out[(size_t)row * N_CLASSES + lane] = z0 - lse;
    if (lane < N_CLASSES - 32)
        out[(size_t)row * N_CLASSES + 32 + lane] = z1 - lse;
}

// ---------------------------------------------------------------------------
// Launch
// ---------------------------------------------------------------------------
extern "C" void kernel_launch(void* const* d_in, const int* in_sizes, int n_in,
                              void* d_out, int out_size) {
    const float* x    = (const float*)d_in[0];
    const int*   nidx = (const int*)d_in[1];
    const int*   eidx = (const int*)d_in[2];
    const float* W1   = (const float*)d_in[3];
    const float* b1   = (const float*)d_in[4];
    const float* W2   = (const float*)d_in[5];
    const float* b2   = (const float*)d_in[6];
    float* out = (float*)d_out;

    float *xw, *ef, *h1, *dinv, *binv;
    int *cnt_n, *cnt_e, *off_n, *off_e, *cur_n, *cur_e, *adj_n, *adj_e, *aux_n, *aux_e;
    cudaGetSymbolAddress((void**)&xw,    g_xw);
    cudaGetSymbolAddress((void**)&ef,    g_ef);
    cudaGetSymbolAddress((void**)&h1,    g_h1);
    cudaGetSymbolAddress((void**)&dinv,  g_dinv);
    cudaGetSymbolAddress((void**)&binv,  g_binv);
    cudaGetSymbolAddress((void**)&cnt_n, g_cnt_n);
    cudaGetSymbolAddress((void**)&cnt_e, g_cnt_e);
    cudaGetSymbolAddress((void**)&off_n, g_off_n);
    cudaGetSymbolAddress((void**)&off_e, g_off_e);
    cudaGetSymbolAddress((void**)&cur_n, g_cur_n);
    cudaGetSymbolAddress((void**)&cur_e, g_cur_e);
    cudaGetSymbolAddress((void**)&adj_n, g_adj_n);
    cudaGetSymbolAddress((void**)&adj_e, g_adj_e);
    cudaGetSymbolAddress((void**)&aux_n, g_aux_n);
    cudaGetSymbolAddress((void**)&aux_e, g_aux_e);

    // ---- degrees ----
    cudaMemsetAsync(cnt_n, 0, N_NODES * sizeof(int));
    cudaMemsetAsync(cnt_e, 0, N_EDGES * sizeof(int));
    degree_kernel<<<(N_INC + 255) / 256, 256>>>(nidx, eidx, cnt_n, cnt_e, N_INC);

    // ---- CSR build: combined scans (invert fused into scan_block2) ----
    scan_block2<<<NB_N + NB_E, 1024>>>(cnt_n, off_n, aux_n, dinv,
                                       cnt_e, off_e, aux_e, binv);
    scan_aux2<<<1, 128>>>(aux_n, aux_e);
    gemm1_kernel<<<(N_NODES + G_RPB - 1) / G_RPB, dim3(8, 8)>>>(x, W1, xw, N_NODES);  // independent; placed here for ncu -s 5
    scan_add2<<<NB_N + NB_E, 1024>>>(off_n, aux_n, cur_n, off_e, aux_e, cur_e);
    fill_csr<<<(N_INC + 255) / 256, 256>>>(nidx, eidx, cur_n, cur_e, adj_n, adj_e, N_INC);

    // ---- layer 1: h1 = relu(Dinv H Binv H^T (x W1) + b1) ----
    gather_kernel<0><<<(N_EDGES + 7) / 8, 256>>>(off_e, adj_e, xw, binv, nullptr, ef, N_EDGES);
    gather_kernel<1><<<(N_NODES + 7) / 8, 256>>>(off_n, adj_n, ef, dinv, b1, h1, N_NODES);

    // ---- layer 2 (aggregate in hidden space; W2 applied post-aggregation) ----
    gather_kernel<0><<<(N_EDGES + 7) / 8, 256>>>(off_e, adj_e, h1, binv, nullptr, ef, N_EDGES);
    gather_w2_logsoftmax<<<(N_NODES + 7) / 8, 256>>>(off_n, adj_n, ef, dinv, W2, b2, out, N_NODES);
}

// round 7
// speedup vs baseline: 1.6324x; 1.0291x over previous
#include <cuda_runtime.h>
#include <cstddef>

#define N_NODES   100000
#define N_EDGES   50000
#define N_INC     3200000
#define D_IN      128
#define D_HID     32
#define N_CLASSES 40

// ---------------------------------------------------------------------------
// Scratch (static device globals)
// ---------------------------------------------------------------------------
__device__ float g_xw[(size_t)N_NODES * D_HID];  // X@W1
__device__ float g_ef[(size_t)N_EDGES * D_HID];  // hyperedge features
__device__ float g_h1[(size_t)N_NODES * D_HID];  // hidden layer
__device__ float g_dinv[N_NODES];
__device__ float g_binv[N_EDGES];

__device__ int g_cnt_n[N_NODES];
__device__ int g_cnt_e[N_EDGES];
__device__ int g_off_n[N_NODES + 1];
__device__ int g_off_e[N_EDGES + 1];
__device__ int g_adj_n[N_INC];    // edge ids grouped by node
__device__ int g_adj_e[N_INC];    // node ids grouped by edge
__device__ int g_rank_n[N_INC];   // rank of pair i within its node bucket
__device__ int g_rank_e[N_INC];   // rank of pair i within its edge bucket
__device__ int g_aux_n[128];
__device__ int g_aux_e[128];

#define NB_N ((N_NODES + 1023) / 1024)   // 98
#define NB_E ((N_EDGES + 1023) / 1024)   // 49

// ---------------------------------------------------------------------------
// Degree counting + per-pair rank capture (the atomic doubles as rank source)
// ---------------------------------------------------------------------------
__global__ void degree_rank_kernel(const int* __restrict__ nidx,
                                   const int* __restrict__ eidx,
                                   int* __restrict__ cn, int* __restrict__ ce,
                                   int* __restrict__ rank_n, int* __restrict__ rank_e,
                                   int n) {
    int i = blockIdx.x * blockDim.x + threadIdx.x;
    if (i < n) {
        rank_n[i] = atomicAdd(cn + nidx[i], 1);
        rank_e[i] = atomicAdd(ce + eidx[i], 1);
    }
}

// ---------------------------------------------------------------------------
// Combined block scan (node + edge arrays in one grid) + fused 1/deg
// ---------------------------------------------------------------------------
__global__ void scan_block2(const int* __restrict__ cnt_n, int* __restrict__ off_n,
                            int* __restrict__ aux_n, float* __restrict__ dinv,
                            const int* __restrict__ cnt_e, int* __restrict__ off_e,
                            int* __restrict__ aux_e, float* __restrict__ binv) {
    __shared__ int sm[1024];
    const int b = blockIdx.x;
    const int* in;  int* out; int* aux; float* inv; int n; int bb;
    if (b < NB_N) { in = cnt_n; out = off_n; aux = aux_n; inv = dinv; n = N_NODES; bb = b; }
    else          { in = cnt_e; out = off_e; aux = aux_e; inv = binv; n = N_EDGES; bb = b - NB_N; }

    const int tid = threadIdx.x;
    const int i = bb * 1024 + tid;
    int v = (i < n) ? in[i] : 0;
    if (i < n) inv[i] = (v > 0) ? (1.0f / (float)v) : 0.0f;
    sm[tid] = v;
    __syncthreads();
#pragma unroll
    for (int o = 1; o < 1024; o <<= 1) {
        int t = (tid >= o) ? sm[tid - o] : 0;
        __syncthreads();
        sm[tid] += t;
        __syncthreads();
    }
    if (i < n) out[i] = sm[tid] - v;            // exclusive
    if (tid == 1023) aux[bb] = sm[1023];
}

// Parallel aux scan (both arrays) — 1 block, 128 threads.
__global__ void scan_aux2(int* __restrict__ aux_n, int* __restrict__ aux_e) {
    __shared__ int sm[128];
    const int t = threadIdx.x;

    int orig = (t < NB_N) ? aux_n[t] : 0;
    sm[t] = orig;
    __syncthreads();
#pragma unroll
    for (int o = 1; o < 128; o <<= 1) {
        int v = (t >= o) ? sm[t - o] : 0;
        __syncthreads();
        sm[t] += v;
        __syncthreads();
    }
    if (t < NB_N) aux_n[t] = sm[t] - orig;
    __syncthreads();

    orig = (t < NB_E) ? aux_e[t] : 0;
    sm[t] = orig;
    __syncthreads();
#pragma unroll
    for (int o = 1; o < 128; o <<= 1) {
        int v = (t >= o) ? sm[t - o] : 0;
        __syncthreads();
        sm[t] += v;
        __syncthreads();
    }
    if (t < NB_E) aux_e[t] = sm[t] - orig;
}

// Combined add-pass; writes the sentinels.
__global__ void scan_add2(int* __restrict__ off_n, const int* __restrict__ aux_n,
                          int* __restrict__ off_e, const int* __restrict__ aux_e) {
    const int b = blockIdx.x;
    if (b < NB_N) {
        int i = b * 1024 + threadIdx.x;
        if (i < N_NODES) off_n[i] += aux_n[b];
        if (i == 0) off_n[N_NODES] = N_INC;
    } else {
        int i = (b - NB_N) * 1024 + threadIdx.x;
        if (i < N_EDGES) off_e[i] += aux_e[b - NB_N];
        if (i == 0) off_e[N_EDGES] = N_INC;
    }
}

// ---------------------------------------------------------------------------
// CSR fill — atomic-free: position = off[key] + precomputed rank.
// ---------------------------------------------------------------------------
__global__ void fill_csr(const int* __restrict__ nidx, const int* __restrict__ eidx,
                         const int* __restrict__ off_n, const int* __restrict__ off_e,
                         const int* __restrict__ rank_n, const int* __restrict__ rank_e,
                         int* __restrict__ adj_n, int* __restrict__ adj_e, int n) {
    int i = blockIdx.x * blockDim.x + threadIdx.x;
    if (i < n) {
        int v = nidx[i], e = eidx[i];
        adj_n[__ldg(off_n + v) + rank_n[i]] = e;
        adj_e[__ldg(off_e + e) + rank_e[i]] = v;
    }
}

// ---------------------------------------------------------------------------
// GEMM1: Y[N,32] = X[N,128] @ W[128,32]. 8 rows x 4 cols per thread.
// blockDim (8,8)=64 threads; block covers 64 rows; dynamic smem ~49 KB.
// Thread rows: ty + 8*r  (r=0..7) -> conflict-free X LDS with XST=132.
// ---------------------------------------------------------------------------
#define G_RPB 64
#define G_XST (D_IN + 4)
#define G_SMEM ((D_IN * D_HID + G_RPB * G_XST) * (int)sizeof(float))  // 50176 B

__global__ void gemm1_kernel(const float* __restrict__ X,
                             const float* __restrict__ W,
                             float* __restrict__ Y, int N) {
    constexpr int K = D_IN, F = D_HID;
    extern __shared__ float smem[];
    float* ws = smem;                // K*F
    float* xs = smem + K * F;        // G_RPB * G_XST
    const int tx = threadIdx.x;      // 0..7 (col quad)
    const int ty = threadIdx.y;      // 0..7 (row slot)
    const int tid = ty * 8 + tx;

    for (int i = tid; i < K * F / 4; i += 64)
        ((float4*)ws)[i] = ((const float4*)W)[i];

    const int row0 = blockIdx.x * G_RPB;
    for (int i = tid; i < G_RPB * (K / 4); i += 64) {
        int r = i / (K / 4), c = i % (K / 4);
        float4 v = make_float4(0.f, 0.f, 0.f, 0.f);
        if (row0 + r < N) v = ((const float4*)X)[(size_t)(row0 + r) * (K / 4) + c];
        *(float4*)&xs[r * G_XST + c * 4] = v;
    }
    __syncthreads();

    float4 acc[8];
#pragma unroll
    for (int r = 0; r < 8; r++) acc[r] = make_float4(0.f, 0.f, 0.f, 0.f);

#pragma unroll
    for (int k = 0; k < K; k += 4) {
        float4 w0 = *(const float4*)&ws[(k + 0) * F + tx * 4];
        float4 w1 = *(const float4*)&ws[(k + 1) * F + tx * 4];
        float4 w2 = *(const float4*)&ws[(k + 2) * F + tx * 4];
        float4 w3 = *(const float4*)&ws[(k + 3) * F + tx * 4];
#pragma unroll
        for (int r = 0; r < 8; r++) {
            float4 xv = *(const float4*)&xs[(ty + 8 * r) * G_XST + k];
            acc[r].x += xv.x * w0.x + xv.y * w1.x + xv.z * w2.x + xv.w * w3.x;
            acc[r].y += xv.x * w0.y + xv.y * w1.y + xv.z * w2.y + xv.w * w3.y;
            acc[r].z += xv.x * w0.z + xv.y * w1.z + xv.z * w2.z + xv.w * w3.z;
            acc[r].w += xv.x * w0.w + xv.y * w1.w + xv.z * w2.w + xv.w * w3.w;
        }
    }
#pragma unroll
    for (int r = 0; r < 8; r++) {
        const int row = row0 + ty + 8 * r;
        if (row < N) *(float4*)&Y[(size_t)row * F + tx * 4] = acc[r];
    }
}

// ---------------------------------------------------------------------------
// float4 CSR gather: warp per dst row; lane = (sub-row r = lane/8, quad q = lane%8).
// MODE 0: dst = scale*sum   MODE 1: dst = relu(scale*sum + bias)
// ---------------------------------------------------------------------------
template <int MODE>
__global__ void gather_kernel(const int* __restrict__ off,
                              const int* __restrict__ adj,
                              const float* __restrict__ src,
                              const float* __restrict__ scale,
                              const float* __restrict__ bias,
                              float* __restrict__ dst, int nrows) {
    const int row  = (blockIdx.x * blockDim.x + threadIdx.x) >> 5;
    const int lane = threadIdx.x & 31;
    if (row >= nrows) return;
    const int r = lane >> 3;          // 0..3 sub-row slot
    const int q = lane & 7;           // 0..7 quad

    const int s = off[row], e = off[row + 1];
    float4 a = make_float4(0.f, 0.f, 0.f, 0.f);
    int j = s;
    for (; j + 8 <= e; j += 8) {
        int m0 = adj[j + r];
        int m1 = adj[j + 4 + r];
        float4 v0 = *(const float4*)(src + (size_t)m0 * D_HID + q * 4);
        float4 v1 = *(const float4*)(src + (size_t)m1 * D_HID + q * 4);
        a.x += v0.x + v1.x; a.y += v0.y + v1.y;
        a.z += v0.z + v1.z; a.w += v0.w + v1.w;
    }
    for (; j < e; j += 4) {
        if (j + r < e) {
            int m = adj[j + r];
            float4 v = *(const float4*)(src + (size_t)m * D_HID + q * 4);
            a.x += v.x; a.y += v.y; a.z += v.z; a.w += v.w;
        }
    }
#pragma unroll
    for (int o = 8; o <= 16; o <<= 1) {
        a.x += __shfl_xor_sync(0xffffffffu, a.x, o);
        a.y += __shfl_xor_sync(0xffffffffu, a.y, o);
        a.z += __shfl_xor_sync(0xffffffffu, a.z, o);
        a.w += __shfl_xor_sync(0xffffffffu, a.w, o);
    }

    if (r == 0) {
        const float f = scale[row];
        if (MODE == 0) {
            a.x *= f; a.y *= f; a.z *= f; a.w *= f;
        } else {
            float4 bb = *(const float4*)(bias + q * 4);
            a.x = fmaxf(a.x * f + bb.x, 0.f);
            a.y = fmaxf(a.y * f + bb.y, 0.f);
            a.z = fmaxf(a.z * f + bb.z, 0.f);
            a.w = fmaxf(a.w * f + bb.w, 0.f);
        }
        *(float4*)(dst + (size_t)row * D_HID + q * 4) = a;
    }
}

// ---------------------------------------------------------------------------
// Fused final: float4 node-gather + @W2 [32,40] + b2 + log_softmax.
// ---------------------------------------------------------------------------
__global__ void gather_w2_logsoftmax(const int* __restrict__ off,
                                     const int* __restrict__ adj,
                                     const float* __restrict__ src,
                                     const float* __restrict__ dinv,
                                     const float* __restrict__ W2,
                                     const float* __restrict__ b2,
                                     float* __restrict__ out, int nrows) {
    __shared__ float w2s[D_HID * N_CLASSES];
    __shared__ float b2s[N_CLASSES];
    {
        const int t = threadIdx.x;
        for (int i = t; i < D_HID * N_CLASSES; i += blockDim.x) w2s[i] = W2[i];
        if (t < N_CLASSES) b2s[t] = b2[t];
    }
    __syncthreads();

    const int row  = (blockIdx.x * blockDim.x + threadIdx.x) >> 5;
    const int lane = threadIdx.x & 31;
    if (row >= nrows) return;
    const int r = lane >> 3;
    const int q = lane & 7;

    const int s = off[row], e = off[row + 1];
    float4 a = make_float4(0.f, 0.f, 0.f, 0.f);
    int j = s;
    for (; j + 8 <= e; j += 8) {
        int m0 = adj[j + r];
        int m1 = adj[j + 4 + r];
        float4 v0 = *(const float4*)(src + (size_t)m0 * D_HID + q * 4);
        float4 v1 = *(const float4*)(src + (size_t)m1 * D_HID + q * 4);
        a.x += v0.x + v1.x; a.y += v0.y + v1.y;
        a.z += v0.z + v1.z; a.w += v0.w + v1.w;
    }
    for (; j < e; j += 4) {
        if (j + r < e) {
            int m = adj[j + r];
            float4 v = *(const float4*)(src + (size_t)m * D_HID + q * 4);
            a.x += v.x; a.y += v.y; a.z += v.z; a.w += v.w;
        }
    }
#pragma unroll
    for (int o = 8; o <= 16; o <<= 1) {
        a.x += __shfl_xor_sync(0xffffffffu, a.x, o);
        a.y += __shfl_xor_sync(0xffffffffu, a.y, o);
        a.z += __shfl_xor_sync(0xffffffffu, a.z, o);
        a.w += __shfl_xor_sync(0xffffffffu, a.w, o);
    }

    const float di = dinv[row];
    a.x *= di; a.y *= di; a.z *= di; a.w *= di;
    // feature k lives on lane q = k>>2 (all r replicas agree), component k&3.

    float z0 = 0.f, z1 = 0.f;
#pragma unroll
    for (int k = 0; k < D_HID; k++) {
        float comp = ((k & 3) == 0) ? a.x : ((k & 3) == 1) ? a.y
                    : ((k & 3) == 2) ? a.z : a.w;
        float ak = __shfl_sync(0xffffffffu, comp, k >> 2);
        z0 += ak * w2s[k * N_CLASSES + lane];
        if (lane < N_CLASSES - 32) z1 += ak * w2s[k * N_CLASSES + 32 + lane];
    }
    z0 += b2s[lane];
    z1 = (lane < N_CLASSES - 32) ? (z1 + b2s[32 + lane]) : -1e30f;

    float m = fmaxf(z0, z1);
#pragma unroll
    for (int o = 16; o; o >>= 1) m = fmaxf(m, __shfl_xor_sync(0xffffffffu, m, o));
    float ex = __expf(z0 - m) + ((lane < N_CLASSES - 32) ? __expf(z1 - m) : 0.f);
#pragma unroll
    for (int o = 16; o; o >>= 1) ex += __shfl_xor_sync(0xffffffffu, ex, o);
    const float lse = __logf(ex) + m;

    out[(size_t)row * N_CLASSES + lane] = z0 - lse;
    if (lane < N_CLASSES - 32)
        out[(size_t)row * N_CLASSES + 32 + lane] = z1 - lse;
}

// ---------------------------------------------------------------------------
// Launch
// ---------------------------------------------------------------------------
extern "C" void kernel_launch(void* const* d_in, const int* in_sizes, int n_in,
                              void* d_out, int out_size) {
    const float* x    = (const float*)d_in[0];
    const int*   nidx = (const int*)d_in[1];
    const int*   eidx = (const int*)d_in[2];
    const float* W1   = (const float*)d_in[3];
    const float* b1   = (const float*)d_in[4];
    const float* W2   = (const float*)d_in[5];
    const float* b2   = (const float*)d_in[6];
    float* out = (float*)d_out;

    float *xw, *ef, *h1, *dinv, *binv;
    int *cnt_n, *cnt_e, *off_n, *off_e, *adj_n, *adj_e, *rank_n, *rank_e, *aux_n, *aux_e;
    cudaGetSymbolAddress((void**)&xw,     g_xw);
    cudaGetSymbolAddress((void**)&ef,     g_ef);
    cudaGetSymbolAddress((void**)&h1,     g_h1);
    cudaGetSymbolAddress((void**)&dinv,   g_dinv);
    cudaGetSymbolAddress((void**)&binv,   g_binv);
    cudaGetSymbolAddress((void**)&cnt_n,  g_cnt_n);
    cudaGetSymbolAddress((void**)&cnt_e,  g_cnt_e);
    cudaGetSymbolAddress((void**)&off_n,  g_off_n);
    cudaGetSymbolAddress((void**)&off_e,  g_off_e);
    cudaGetSymbolAddress((void**)&adj_n,  g_adj_n);
    cudaGetSymbolAddress((void**)&adj_e,  g_adj_e);
    cudaGetSymbolAddress((void**)&rank_n, g_rank_n);
    cudaGetSymbolAddress((void**)&rank_e, g_rank_e);
    cudaGetSymbolAddress((void**)&aux_n,  g_aux_n);
    cudaGetSymbolAddress((void**)&aux_e,  g_aux_e);

    static int smem_set = 0;
    cudaFuncSetAttribute(gemm1_kernel,
                         cudaFuncAttributeMaxDynamicSharedMemorySize, G_SMEM);
    (void)smem_set;

    // ---- degrees + per-pair ranks ----
    cudaMemsetAsync(cnt_n, 0, N_NODES * sizeof(int));
    cudaMemsetAsync(cnt_e, 0, N_EDGES * sizeof(int));
    degree_rank_kernel<<<(N_INC + 255) / 256, 256>>>(nidx, eidx, cnt_n, cnt_e,
                                                     rank_n, rank_e, N_INC);

    // ---- CSR build: combined scans (invert fused into scan_block2) ----
    scan_block2<<<NB_N + NB_E, 1024>>>(cnt_n, off_n, aux_n, dinv,
                                       cnt_e, off_e, aux_e, binv);
    scan_aux2<<<1, 128>>>(aux_n, aux_e);
    gemm1_kernel<<<(N_NODES + G_RPB - 1) / G_RPB, dim3(8, 8), G_SMEM>>>(x, W1, xw, N_NODES);  // independent; placed for ncu -s 5
    scan_add2<<<NB_N + NB_E, 1024>>>(off_n, aux_n, off_e, aux_e);
    fill_csr<<<(N_INC + 255) / 256, 256>>>(nidx, eidx, off_n, off_e,
                                           rank_n, rank_e, adj_n, adj_e, N_INC);

    // ---- layer 1: h1 = relu(Dinv H Binv H^T (x W1) + b1) ----
    gather_kernel<0><<<(N_EDGES + 7) / 8, 256>>>(off_e, adj_e, xw, binv, nullptr, ef, N_EDGES);
    gather_kernel<1><<<(N_NODES + 7) / 8, 256>>>(off_n, adj_n, ef, dinv, b1, h1, N_NODES);

    // ---- layer 2 (aggregate in hidden space; W2 applied post-aggregation) ----
    gather_kernel<0><<<(N_EDGES + 7) / 8, 256>>>(off_e, adj_e, h1, binv, nullptr, ef, N_EDGES);
    gather_w2_logsoftmax<<<(N_NODES + 7) / 8, 256>>>(off_n, adj_n, ef, dinv, W2, b2, out, N_NODES);
}